// round 4
// baseline (speedup 1.0000x reference)
#include <cuda_runtime.h>

// Problem constants
#define BB   4      // batch
#define CIN  3
#define C1   32     // conv1 out channels (16x16 spatial)
#define C2   64     // conv2 out channels (8x8 spatial)
#define MM   512    // hopfield memory slots
#define DD   64     // token dim (== C2)
#define NTOK 4      // tokens per hopfield block
#define HTHR 512    // hopfield threads per block

// Scratch (allocation-free rule: __device__ globals)
__device__ float g_a1[BB*C1*16*16];   // relu(conv1(x)+b1)
__device__ float g_v1[BB*C1*16*16];   // mask1 * conv1(x)   (JVP, no bias)
__device__ float g_zq[BB*C2*64];      // masked JVP output (B, C2, 64 spatial)
__device__ float g_Wc[DD*DD];         // Wv @ Wo (folded projection)

// ---------------------------------------------------------------------------
// Kernel 1: conv1 (stride 2, pad 1, k=4) forward + JVP value.
// ---------------------------------------------------------------------------
__global__ void conv1_kernel(const float* __restrict__ x,
                             const float* __restrict__ w,
                             const float* __restrict__ bias) {
    int idx = blockIdx.x * blockDim.x + threadIdx.x;
    if (idx >= BB*C1*16*16) return;
    int ox = idx & 15;
    int oy = (idx >> 4) & 15;
    int oc = (idx >> 8) & 31;
    int b  = idx >> 13;

    float s = 0.f;
    #pragma unroll
    for (int ic = 0; ic < CIN; ic++) {
        const float* xp = x + (b*CIN + ic) * 1024;
        const float* wp = w + (oc*CIN + ic) * 16;
        #pragma unroll
        for (int ky = 0; ky < 4; ky++) {
            int iy = oy*2 - 1 + ky;
            if (iy < 0 || iy >= 32) continue;
            #pragma unroll
            for (int kx = 0; kx < 4; kx++) {
                int ix = ox*2 - 1 + kx;
                if (ix < 0 || ix >= 32) continue;
                s += __ldg(&xp[iy*32 + ix]) * __ldg(&wp[ky*4 + kx]);
            }
        }
    }
    float pre = s + bias[oc];
    bool on = pre > 0.f;
    g_a1[idx] = on ? pre : 0.f;
    g_v1[idx] = on ? s   : 0.f;
}

// ---------------------------------------------------------------------------
// Kernel 2: conv2 forward-mask + JVP, ic split across even/odd lanes.
// ---------------------------------------------------------------------------
__global__ void conv2_kernel(const float* __restrict__ w,
                             const float* __restrict__ bias) {
    int gid = blockIdx.x * blockDim.x + threadIdx.x;
    if (gid >= 2*BB*C2*64) return;
    int h = gid & 1;          // ic-half
    int p = gid >> 1;         // output index
    int ox = p & 7;
    int oy = (p >> 3) & 7;
    int oc = (p >> 6) & 63;
    int b  = p >> 12;

    float sA = 0.f, sV = 0.f;
    int ic0 = h * 16;
    #pragma unroll 4
    for (int ic = ic0; ic < ic0 + 16; ic++) {
        const float* ap = g_a1 + (b*C1 + ic) * 256;
        const float* vp = g_v1 + (b*C1 + ic) * 256;
        const float* wp = w + (oc*C1 + ic) * 16;
        #pragma unroll
        for (int ky = 0; ky < 4; ky++) {
            int iy = oy*2 - 1 + ky;
            if (iy < 0 || iy >= 16) continue;
            #pragma unroll
            for (int kx = 0; kx < 4; kx++) {
                int ix = ox*2 - 1 + kx;
                if (ix < 0 || ix >= 16) continue;
                float wv = __ldg(&wp[ky*4 + kx]);
                sA += __ldg(&ap[iy*16 + ix]) * wv;
                sV += __ldg(&vp[iy*16 + ix]) * wv;
            }
        }
    }
    sA += __shfl_xor_sync(0xFFFFFFFFu, sA, 1);
    sV += __shfl_xor_sync(0xFFFFFFFFu, sV, 1);
    if (h == 0) {
        float pre = sA + bias[oc];
        g_zq[(b*C2 + oc) * 64 + (oy*8 + ox)] = (pre > 0.f) ? sV : 0.f;
    }
}

// ---------------------------------------------------------------------------
// Kernel 3: Wc = Wv @ Wo  (64x64).  Grid 64 blocks x 64 threads.
// ---------------------------------------------------------------------------
__global__ void wc_kernel(const float* __restrict__ Wv,
                          const float* __restrict__ Wo) {
    int d = blockIdx.x;
    int e = threadIdx.x;
    __shared__ float row[DD];
    row[e] = Wv[d*DD + e];
    __syncthreads();
    float s = 0.f;
    #pragma unroll
    for (int k = 0; k < DD; k++)
        s += row[k] * Wo[k*DD + e];    // coalesced over e
    g_Wc[d*DD + e] = s;
}

// ---------------------------------------------------------------------------
// Kernel 4: Hopfield retrieval, 4 tokens/block, 512 threads, grid (16, B).
// out[j] = softmax(t_j . lookup^T / 8) @ lookup @ Wc, Wc = Wv@Wo.
// lookup staged once in smem (pad-65 rows) with MLP-8 batched loads; all
// subsequent math (scores, retrieval, projection) runs out of smem.
// ---------------------------------------------------------------------------
__global__ void hopfield_kernel(const float* __restrict__ lookup,
                                float* __restrict__ out) {
    extern __shared__ float smem[];
    float*  Lsm   = smem;                        // 512*65
    float4* pS4   = (float4*)(smem + MM*65);     // 512: probs [m] x 4 tok
    float4* red4  = pS4 + MM;                    // 512 (only 16+1 used)
    float4* part4 = red4 + MM;                   // 512: retrieval partials
    float*  WcS   = (float*)(part4 + MM);        // 64*64
    float*  tS    = WcS + DD*DD;                 // tokens [d][j]
    float*  tmpS  = tS + DD*NTOK;                // retrieved [j][d]
    float*  oS    = tmpS + NTOK*DD;              // out [e][j]

    int tid  = threadIdx.x;
    int lane = tid & 31;
    int wid  = tid >> 5;
    int n0   = blockIdx.x * NTOK;
    int b    = blockIdx.y;

    // --- stage lookup: 8192 float4, 16/thread, batches of 8 (MLP=8) ---
    const float4* L4 = (const float4*)lookup;
    #pragma unroll
    for (int batch = 0; batch < 2; batch++) {
        float4 v[8];
        #pragma unroll
        for (int u = 0; u < 8; u++)
            v[u] = __ldg(&L4[(batch*8 + u)*HTHR + tid]);
        #pragma unroll
        for (int u = 0; u < 8; u++) {
            int f = (batch*8 + u)*HTHR + tid;        // float4 index
            float* p = &Lsm[(f >> 4)*65 + (f & 15)*4];
            p[0] = v[u].x; p[1] = v[u].y; p[2] = v[u].z; p[3] = v[u].w;
        }
    }
    // --- stage Wc (1024 float4, 2/thread) ---
    {
        const float4* W4 = (const float4*)g_Wc;
        float4 a = __ldg(&W4[tid]);
        float4 c = __ldg(&W4[tid + HTHR]);
        ((float4*)WcS)[tid]        = a;
        ((float4*)WcS)[tid + HTHR] = c;
    }
    // --- stage tokens transposed: tS[d][j] ---
    if (tid < DD*NTOK) {
        int j = tid & 3, d = tid >> 2;
        tS[d*NTOK + j] = g_zq[(b*C2 + d)*64 + n0 + j];
    }
    __syncthreads();

    // --- scores: thread owns row m = tid, all 4 tokens ---
    float a0 = 0.f, a1 = 0.f, a2 = 0.f, a3 = 0.f;
    {
        const float* lp = &Lsm[tid*65];
        #pragma unroll 16
        for (int d = 0; d < DD; d++) {
            float4 tv = *(const float4*)&tS[d*NTOK];
            float l = lp[d];
            a0 += l*tv.x; a1 += l*tv.y; a2 += l*tv.z; a3 += l*tv.w;
        }
    }
    const float scale = 0.125f;  // 1/sqrt(64)
    a0 *= scale; a1 *= scale; a2 *= scale; a3 *= scale;

    // --- block max: warp shfl + one cross-warp stage ---
    {
        float4 m4 = make_float4(a0, a1, a2, a3);
        #pragma unroll
        for (int o = 16; o > 0; o >>= 1) {
            m4.x = fmaxf(m4.x, __shfl_xor_sync(0xFFFFFFFFu, m4.x, o));
            m4.y = fmaxf(m4.y, __shfl_xor_sync(0xFFFFFFFFu, m4.y, o));
            m4.z = fmaxf(m4.z, __shfl_xor_sync(0xFFFFFFFFu, m4.z, o));
            m4.w = fmaxf(m4.w, __shfl_xor_sync(0xFFFFFFFFu, m4.w, o));
        }
        if (lane == 0) red4[wid] = m4;
    }
    __syncthreads();
    float4 MX;
    {
        if (wid == 0) {
            float4 v = (lane < 16) ? red4[lane]
                                   : make_float4(-1e30f, -1e30f, -1e30f, -1e30f);
            #pragma unroll
            for (int o = 16; o > 0; o >>= 1) {
                v.x = fmaxf(v.x, __shfl_xor_sync(0xFFFFFFFFu, v.x, o));
                v.y = fmaxf(v.y, __shfl_xor_sync(0xFFFFFFFFu, v.y, o));
                v.z = fmaxf(v.z, __shfl_xor_sync(0xFFFFFFFFu, v.z, o));
                v.w = fmaxf(v.w, __shfl_xor_sync(0xFFFFFFFFu, v.w, o));
            }
            if (lane == 0) red4[16] = v;
        }
        __syncthreads();
        MX = red4[16];
    }

    // --- exp + block sum ---
    float4 e4 = make_float4(__expf(a0 - MX.x), __expf(a1 - MX.y),
                            __expf(a2 - MX.z), __expf(a3 - MX.w));
    pS4[tid] = e4;
    {
        float4 s4 = e4;
        #pragma unroll
        for (int o = 16; o > 0; o >>= 1) {
            s4.x += __shfl_xor_sync(0xFFFFFFFFu, s4.x, o);
            s4.y += __shfl_xor_sync(0xFFFFFFFFu, s4.y, o);
            s4.z += __shfl_xor_sync(0xFFFFFFFFu, s4.z, o);
            s4.w += __shfl_xor_sync(0xFFFFFFFFu, s4.w, o);
        }
        if (lane == 0) red4[32 + wid] = s4;
    }
    __syncthreads();
    float4 SUM;
    {
        if (wid == 0) {
            float4 v = (lane < 16) ? red4[32 + lane]
                                   : make_float4(0.f, 0.f, 0.f, 0.f);
            #pragma unroll
            for (int o = 16; o > 0; o >>= 1) {
                v.x += __shfl_xor_sync(0xFFFFFFFFu, v.x, o);
                v.y += __shfl_xor_sync(0xFFFFFFFFu, v.y, o);
                v.z += __shfl_xor_sync(0xFFFFFFFFu, v.z, o);
                v.w += __shfl_xor_sync(0xFFFFFFFFu, v.w, o);
            }
            if (lane == 0) red4[48] = v;
        }
        __syncthreads();
        SUM = red4[48];
    }

    // --- retrieval from smem: part[c][d] = sum over 64 m of p[m]*L[m][d] ---
    {
        int d = tid & 63, c = tid >> 6;   // 8 chunks of 64 m
        float r0 = 0.f, r1 = 0.f, r2 = 0.f, r3 = 0.f;
        int m0 = c * 64;
        #pragma unroll 8
        for (int mm = 0; mm < 64; mm++) {
            float4 p = pS4[m0 + mm];              // broadcast
            float  l = Lsm[(m0 + mm)*65 + d];     // conflict-free
            r0 += p.x*l; r1 += p.y*l; r2 += p.z*l; r3 += p.w*l;
        }
        part4[c*64 + d] = make_float4(r0, r1, r2, r3);
    }
    __syncthreads();
    if (tid < NTOK*DD) {
        int j = tid >> 6, d = tid & 63;
        const float* pf = (const float*)part4;
        float s = 0.f;
        #pragma unroll
        for (int c = 0; c < 8; c++)
            s += pf[(c*64 + d)*4 + j];
        float inv = 1.f / ((j == 0) ? SUM.x : (j == 1) ? SUM.y
                          : (j == 2) ? SUM.z : SUM.w);
        tmpS[j*DD + d] = s * inv;
    }
    __syncthreads();

    // --- projection: out[j][e] = sum_d tmp[j][d] * Wc[d][e] ---
    if (tid < NTOK*DD) {
        int j = tid >> 6, e = tid & 63;
        float o = 0.f;
        const float* tp = &tmpS[j*DD];
        #pragma unroll 16
        for (int d = 0; d < DD; d++)
            o += tp[d] * WcS[d*DD + e];           // bcast + conflict-free
        oS[e*NTOK + j] = o;
    }
    __syncthreads();
    if (tid < DD) {
        float4 ov = ((float4*)oS)[tid];
        *(float4*)&out[(b*C2 + tid)*64 + n0] = ov;
    }
}

// ---------------------------------------------------------------------------
extern "C" void kernel_launch(void* const* d_in, const int* in_sizes, int n_in,
                              void* d_out, int out_size) {
    const float* x       = (const float*)d_in[0];
    const float* conv1_w = (const float*)d_in[1];
    const float* conv1_b = (const float*)d_in[2];
    const float* conv2_w = (const float*)d_in[3];
    const float* conv2_b = (const float*)d_in[4];
    const float* lookup  = (const float*)d_in[5];
    const float* Wv      = (const float*)d_in[6];
    const float* Wo      = (const float*)d_in[7];
    float* out = (float*)d_out;

    const int smem_floats = MM*65 + MM*4*3 /*pS4,red4,part4*/ + DD*DD
                          + DD*NTOK + NTOK*DD + DD*NTOK;
    const size_t smem_bytes = smem_floats * sizeof(float);
    cudaFuncSetAttribute(hopfield_kernel,
                         cudaFuncAttributeMaxDynamicSharedMemorySize,
                         (int)smem_bytes);

    conv1_kernel<<<(BB*C1*16*16 + 255)/256, 256>>>(x, conv1_w, conv1_b);
    wc_kernel<<<DD, DD>>>(Wv, Wo);                 // independent of conv path
    conv2_kernel<<<(2*BB*C2*64 + 255)/256, 256>>>(conv2_w, conv2_b);
    hopfield_kernel<<<dim3(64/NTOK, BB), HTHR, smem_bytes>>>(lookup, out);
}

// round 5
// speedup vs baseline: 1.4624x; 1.4624x over previous
#include <cuda_runtime.h>

// Problem constants
#define BB   4      // batch
#define CIN  3
#define C1   32     // conv1 out channels (16x16 spatial)
#define C2   64     // conv2 out channels (8x8 spatial)
#define MM   512    // hopfield memory slots
#define DD   64     // token dim (== C2)
#define NTOK 2      // tokens per hopfield block
#define HTHR 512    // hopfield threads per block
#define LSTR 68     // Lsm row stride (floats): 16B-aligned, conflict-free

// Scratch (allocation-free rule: __device__ globals)
__device__ float g_av[BB*C1*16*16*2]; // interleaved {a1, v1}
__device__ float g_zq[BB*C2*64];      // masked JVP output (B, C2, 64 spatial)
__device__ float g_Wc[DD*DD];         // Wv @ Wo (folded projection)

// ---------------------------------------------------------------------------
// Kernel 1: fused conv1 (blocks 0..127) + Wc = Wv@Wo (blocks 128..143).
// ---------------------------------------------------------------------------
__global__ void conv1_wc_kernel(const float* __restrict__ x,
                                const float* __restrict__ w,
                                const float* __restrict__ bias,
                                const float* __restrict__ Wv,
                                const float* __restrict__ Wo) {
    if (blockIdx.x < 128) {
        int idx = blockIdx.x * 256 + threadIdx.x;   // < 32768
        int ox = idx & 15;
        int oy = (idx >> 4) & 15;
        int oc = (idx >> 8) & 31;
        int b  = idx >> 13;

        float s = 0.f;
        #pragma unroll
        for (int ic = 0; ic < CIN; ic++) {
            const float* xp = x + (b*CIN + ic) * 1024;
            const float* wp = w + (oc*CIN + ic) * 16;
            #pragma unroll
            for (int ky = 0; ky < 4; ky++) {
                int iy = oy*2 - 1 + ky;
                if (iy < 0 || iy >= 32) continue;
                #pragma unroll
                for (int kx = 0; kx < 4; kx++) {
                    int ix = ox*2 - 1 + kx;
                    if (ix < 0 || ix >= 32) continue;
                    s += __ldg(&xp[iy*32 + ix]) * __ldg(&wp[ky*4 + kx]);
                }
            }
        }
        float pre = s + bias[oc];
        bool on = pre > 0.f;
        float2 av = make_float2(on ? pre : 0.f, on ? s : 0.f);
        *(float2*)&g_av[2*idx] = av;
    } else {
        // Wc: 16 blocks, each computes 4 rows of Wc (64x64)
        int wb = blockIdx.x - 128;           // 0..15
        int dl = threadIdx.x >> 6;           // 0..3
        int e  = threadIdx.x & 63;
        int d  = wb*4 + dl;
        float s = 0.f;
        #pragma unroll 16
        for (int k = 0; k < DD; k++)
            s += __ldg(&Wv[d*DD + k]) * __ldg(&Wo[k*DD + e]);
        g_Wc[d*DD + e] = s;
    }
}

// ---------------------------------------------------------------------------
// Kernel 2: conv2 forward-mask + JVP, ic split across even/odd lanes.
// Interleaved {a1,v1} loads: one LDG.64 per tap.
// ---------------------------------------------------------------------------
__global__ void conv2_kernel(const float* __restrict__ w,
                             const float* __restrict__ bias) {
    int gid = blockIdx.x * blockDim.x + threadIdx.x;
    if (gid >= 2*BB*C2*64) return;
    int h = gid & 1;          // ic-half
    int p = gid >> 1;         // output index
    int ox = p & 7;
    int oy = (p >> 3) & 7;
    int oc = (p >> 6) & 63;
    int b  = p >> 12;

    float sA = 0.f, sV = 0.f;
    int ic0 = h * 16;
    #pragma unroll 4
    for (int ic = ic0; ic < ic0 + 16; ic++) {
        const float2* avp = (const float2*)g_av + (b*C1 + ic) * 256;
        const float*  wp  = w + (oc*C1 + ic) * 16;
        #pragma unroll
        for (int ky = 0; ky < 4; ky++) {
            int iy = oy*2 - 1 + ky;
            if (iy < 0 || iy >= 16) continue;
            #pragma unroll
            for (int kx = 0; kx < 4; kx++) {
                int ix = ox*2 - 1 + kx;
                if (ix < 0 || ix >= 16) continue;
                float wv = __ldg(&wp[ky*4 + kx]);
                float2 av = __ldg(&avp[iy*16 + ix]);
                sA += av.x * wv;
                sV += av.y * wv;
            }
        }
    }
    sA += __shfl_xor_sync(0xFFFFFFFFu, sA, 1);
    sV += __shfl_xor_sync(0xFFFFFFFFu, sV, 1);
    if (h == 0) {
        float pre = sA + bias[oc];
        g_zq[(b*C2 + oc) * 64 + (oy*8 + ox)] = (pre > 0.f) ? sV : 0.f;
    }
}

// ---------------------------------------------------------------------------
// Kernel 3: Hopfield retrieval, 2 tokens/block, 512 threads, grid (32, B).
// out[j] = softmax(t_j . lookup^T / 8) @ lookup @ Wc, Wc = Wv@Wo.
// ---------------------------------------------------------------------------
__global__ __launch_bounds__(HTHR, 1)
void hopfield_kernel(const float* __restrict__ lookup,
                     float* __restrict__ out) {
    extern __shared__ float smem[];
    float*  Lsm   = smem;                          // 512*68
    float*  WcS   = Lsm + MM*LSTR;                 // 64*64
    float2* pS2   = (float2*)(WcS + DD*DD);        // 512 probs (2 tok)
    float2* part2 = pS2 + MM;                      // 512 retrieval partials
    float*  tS    = (float*)(part2 + MM);          // tokens [d][j], 128
    float2* oS2   = (float2*)(tS + DD*NTOK);       // out [e], 64 float2
    float2* red2  = oS2 + DD;                      // 18 float2 used

    int tid  = threadIdx.x;
    int lane = tid & 31;
    int wid  = tid >> 5;
    int n0   = blockIdx.x * NTOK;
    int b    = blockIdx.y;

    // --- stage lookup: 8192 float4, 16/thread, batches of 8 (MLP=8) ---
    const float4* L4   = (const float4*)lookup;
    float4*       Lsm4 = (float4*)Lsm;             // row stride 17 float4
    #pragma unroll
    for (int batch = 0; batch < 2; batch++) {
        float4 v[8];
        #pragma unroll
        for (int u = 0; u < 8; u++)
            v[u] = __ldg(&L4[(batch*8 + u)*HTHR + tid]);
        #pragma unroll
        for (int u = 0; u < 8; u++) {
            int f = (batch*8 + u)*HTHR + tid;      // float4 index
            Lsm4[(f >> 4)*17 + (f & 15)] = v[u];
        }
    }
    // --- stage Wc (1024 float4, 2/thread) ---
    {
        const float4* W4 = (const float4*)g_Wc;
        ((float4*)WcS)[tid]        = __ldg(&W4[tid]);
        ((float4*)WcS)[tid + HTHR] = __ldg(&W4[tid + HTHR]);
    }
    // --- stage tokens transposed: tS[d][j] ---
    if (tid < DD*NTOK) {
        int j = tid & 1, d = tid >> 1;
        tS[d*NTOK + j] = g_zq[(b*C2 + d)*64 + n0 + j];
    }
    __syncthreads();

    // --- scores: thread owns row m = tid, 2 tokens ---
    float a0 = 0.f, a1 = 0.f;
    {
        const float4* lrow = (const float4*)&Lsm[tid*LSTR];
        #pragma unroll
        for (int q = 0; q < 16; q++) {
            float4 l  = lrow[q];
            float4 t0 = *(const float4*)&tS[q*8];      // {t[4q].j0,.j1, t[4q+1].j0,.j1}
            float4 t1 = *(const float4*)&tS[q*8 + 4];
            a0 += l.x*t0.x + l.y*t0.z + l.z*t1.x + l.w*t1.z;
            a1 += l.x*t0.y + l.y*t0.w + l.z*t1.y + l.w*t1.w;
        }
    }
    a0 *= 0.125f; a1 *= 0.125f;   // 1/sqrt(64)

    // --- block max ---
    {
        float mx0 = a0, mx1 = a1;
        #pragma unroll
        for (int o = 16; o > 0; o >>= 1) {
            mx0 = fmaxf(mx0, __shfl_xor_sync(0xFFFFFFFFu, mx0, o));
            mx1 = fmaxf(mx1, __shfl_xor_sync(0xFFFFFFFFu, mx1, o));
        }
        if (lane == 0) red2[wid] = make_float2(mx0, mx1);
    }
    __syncthreads();
    if (tid < 32) {
        float2 v = (lane < 16) ? red2[lane] : make_float2(-1e30f, -1e30f);
        #pragma unroll
        for (int o = 8; o > 0; o >>= 1) {
            v.x = fmaxf(v.x, __shfl_xor_sync(0xFFFFFFFFu, v.x, o));
            v.y = fmaxf(v.y, __shfl_xor_sync(0xFFFFFFFFu, v.y, o));
        }
        if (lane == 0) red2[16] = v;
    }
    __syncthreads();
    float2 MX = red2[16];

    // --- exp + block sum ---
    float e0 = __expf(a0 - MX.x);
    float e1 = __expf(a1 - MX.y);
    pS2[tid] = make_float2(e0, e1);
    {
        float s0 = e0, s1 = e1;
        #pragma unroll
        for (int o = 16; o > 0; o >>= 1) {
            s0 += __shfl_xor_sync(0xFFFFFFFFu, s0, o);
            s1 += __shfl_xor_sync(0xFFFFFFFFu, s1, o);
        }
        if (lane == 0) red2[wid] = make_float2(s0, s1);
    }
    __syncthreads();
    if (tid < 32) {
        float2 v = (lane < 16) ? red2[lane] : make_float2(0.f, 0.f);
        #pragma unroll
        for (int o = 8; o > 0; o >>= 1) {
            v.x += __shfl_xor_sync(0xFFFFFFFFu, v.x, o);
            v.y += __shfl_xor_sync(0xFFFFFFFFu, v.y, o);
        }
        if (lane == 0) red2[17] = v;
    }
    __syncthreads();
    float2 SUM = red2[17];

    // --- retrieval: part[c][d] = sum over 64 m of p[m]*L[m][d] ---
    {
        int d = tid & 63, c = tid >> 6;   // 8 chunks of 64 m
        float r0 = 0.f, r1 = 0.f;
        int m0 = c * 64;
        #pragma unroll 8
        for (int mm = 0; mm < 64; mm++) {
            float2 p = pS2[m0 + mm];              // broadcast
            float  l = Lsm[(m0 + mm)*LSTR + d];   // conflict-free
            r0 += p.x*l; r1 += p.y*l;
        }
        part2[c*64 + d] = make_float2(r0, r1);
    }
    __syncthreads();
    if (tid < NTOK*DD) {
        int j = tid >> 6, d = tid & 63;
        const float* pf = (const float*)part2;
        float s = 0.f;
        #pragma unroll
        for (int c = 0; c < 8; c++)
            s += pf[(c*64 + d)*2 + j];
        float inv = 1.f / (j ? SUM.y : SUM.x);
        tS[j*DD + d] = s * inv;                   // reuse tS as tmp[j][d]
    }
    __syncthreads();

    // --- projection: out[j][e] = sum_d tmp[j][d] * Wc[d][e] ---
    if (tid < NTOK*DD) {
        int j = tid >> 6, e = tid & 63;
        float o = 0.f;
        const float* tp = &tS[j*DD];
        #pragma unroll 16
        for (int d = 0; d < DD; d++)
            o += tp[d] * WcS[d*DD + e];           // bcast + conflict-free
        float* od = (float*)&oS2[e];
        od[j] = o;
    }
    __syncthreads();
    if (tid < DD) {
        float2 ov = oS2[tid];
        *(float2*)&out[(b*C2 + tid)*64 + n0] = ov;
    }
}

// ---------------------------------------------------------------------------
extern "C" void kernel_launch(void* const* d_in, const int* in_sizes, int n_in,
                              void* d_out, int out_size) {
    const float* x       = (const float*)d_in[0];
    const float* conv1_w = (const float*)d_in[1];
    const float* conv1_b = (const float*)d_in[2];
    const float* conv2_w = (const float*)d_in[3];
    const float* conv2_b = (const float*)d_in[4];
    const float* lookup  = (const float*)d_in[5];
    const float* Wv      = (const float*)d_in[6];
    const float* Wo      = (const float*)d_in[7];
    float* out = (float*)d_out;

    const int smem_floats = MM*LSTR + DD*DD + MM*2 /*pS2*/ + MM*2 /*part2*/
                          + DD*NTOK + DD*2 /*oS2*/ + 40 /*red2*/;
    const size_t smem_bytes = smem_floats * sizeof(float);

    // One-time attribute setup (host-side; runs during capture only).
    cudaFuncSetAttribute(hopfield_kernel,
                         cudaFuncAttributeMaxDynamicSharedMemorySize,
                         (int)smem_bytes);
    // Pin all kernels to the same (max) smem carveout so graph replay never
    // toggles the L1/SMEM split between nodes.
    cudaFuncSetAttribute(conv1_wc_kernel,
                         cudaFuncAttributePreferredSharedMemoryCarveout, 100);
    cudaFuncSetAttribute(conv2_kernel,
                         cudaFuncAttributePreferredSharedMemoryCarveout, 100);
    cudaFuncSetAttribute(hopfield_kernel,
                         cudaFuncAttributePreferredSharedMemoryCarveout, 100);

    conv1_wc_kernel<<<144, 256>>>(x, conv1_w, conv1_b, Wv, Wo);
    conv2_kernel<<<(2*BB*C2*64 + 255)/256, 256>>>(conv2_w, conv2_b);
    hopfield_kernel<<<dim3(DD/NTOK, BB), HTHR, smem_bytes>>>(lookup, out);
}

// round 6
// speedup vs baseline: 1.7512x; 1.1974x over previous
#include <cuda_runtime.h>

// Problem constants
#define BB   4      // batch
#define CIN  3
#define C1   32     // conv1 out channels (16x16 spatial)
#define C2   64     // conv2 out channels (8x8 spatial)
#define MM   512    // hopfield memory slots
#define DD   64     // token dim (== C2)
#define NTOK 2      // tokens per hopfield block
#define THR  512    // threads per block
#define NBLK 128    // blocks (1 per SM, <= 148 -> all co-resident)
#define LSTR 68     // Lsm row stride (floats): 16B-aligned, conflict-free

// Scratch (allocation-free rule: __device__ globals)
__device__ float g_av[BB*C1*16*16*2]; // interleaved {a1, v1}
__device__ float g_zq[BB*C2*64];      // masked JVP output (B, C2, 64 spatial)
__device__ float g_Wc[DD*DD];         // Wv @ Wo (folded projection)
__device__ unsigned g_bar;            // cumulative grid-barrier ticket counter

// Software grid barrier: all NBLK blocks are co-resident (1 block/SM,
// NBLK <= SM count), so spinning is deadlock-free. Cumulative tickets stay
// 128-aligned across graph replays (exactly 2 barriers * 128 arrivals per
// launch; 2^32 % 128 == 0 so wrap is safe).
__device__ __forceinline__ void grid_barrier() {
    __syncthreads();
    if (threadIdx.x == 0) {
        __threadfence();
        unsigned ticket = atomicAdd(&g_bar, 1u);
        unsigned target = (ticket & ~(unsigned)(NBLK - 1)) + NBLK;
        while ((int)(*(volatile unsigned*)&g_bar - target) < 0) { }
        __threadfence();
    }
    __syncthreads();
}

// ---------------------------------------------------------------------------
// Single fused kernel: conv1+Wc | barrier | conv2 | barrier | hopfield
// ---------------------------------------------------------------------------
__global__ __launch_bounds__(THR, 1)
void fused_kernel(const float* __restrict__ x,
                  const float* __restrict__ w1,
                  const float* __restrict__ b1,
                  const float* __restrict__ w2,
                  const float* __restrict__ b2,
                  const float* __restrict__ lookup,
                  float* __restrict__ out) {
    extern __shared__ float smem[];
    float*  Lsm   = smem;                          // 512*68
    float*  WcS   = Lsm + MM*LSTR;                 // 64*64
    float2* pS2   = (float2*)(WcS + DD*DD);        // 512 probs (2 tok)
    float2* part2 = pS2 + MM;                      // 512 retrieval partials
    float*  tS    = (float*)(part2 + MM);          // tokens [d][j], 128
    float2* oS2   = (float2*)(tS + DD*NTOK);       // out [e], 64 float2
    float2* red2  = oS2 + DD;                      // 18 float2 used

    int tid  = threadIdx.x;
    int lane = tid & 31;
    int wid  = tid >> 5;
    int gtid = blockIdx.x * THR + tid;             // 0..65535

    // ===== Phase 0: stage lookup into smem (overlaps with conv1 latency) ===
    {
        const float4* L4   = (const float4*)lookup;
        float4*       Lsm4 = (float4*)Lsm;         // row stride 17 float4
        #pragma unroll
        for (int batch = 0; batch < 2; batch++) {
            float4 v[8];
            #pragma unroll
            for (int u = 0; u < 8; u++)
                v[u] = __ldg(&L4[(batch*8 + u)*THR + tid]);
            #pragma unroll
            for (int u = 0; u < 8; u++) {
                int f = (batch*8 + u)*THR + tid;   // float4 index
                Lsm4[(f >> 4)*17 + (f & 15)] = v[u];
            }
        }
    }

    // ===== Phase 1: conv1 (32768 thr) + Wc = Wv@Wo (4096 thr) ==============
    if (gtid < BB*C1*16*16) {
        int idx = gtid;
        int ox = idx & 15;
        int oy = (idx >> 4) & 15;
        int oc = (idx >> 8) & 31;
        int b  = idx >> 13;

        float s = 0.f;
        #pragma unroll
        for (int ic = 0; ic < CIN; ic++) {
            const float* xp = x + (b*CIN + ic) * 1024;
            const float* wp = w1 + (oc*CIN + ic) * 16;
            #pragma unroll
            for (int ky = 0; ky < 4; ky++) {
                int iy = oy*2 - 1 + ky;
                if (iy < 0 || iy >= 32) continue;
                #pragma unroll
                for (int kx = 0; kx < 4; kx++) {
                    int ix = ox*2 - 1 + kx;
                    if (ix < 0 || ix >= 32) continue;
                    s += __ldg(&xp[iy*32 + ix]) * __ldg(&wp[ky*4 + kx]);
                }
            }
        }
        float pre = s + b1[oc];
        bool on = pre > 0.f;
        *(float2*)&g_av[2*idx] = make_float2(on ? pre : 0.f, on ? s : 0.f);
    } else if (gtid < BB*C1*16*16 + DD*DD) {
        // Wc row d, col e  (note: args w2,b2 unused here; Wv/Wo come via
        // the dedicated pointers below)
        // handled in second kernel arg set — see wc pointers passed globally
    }
    // (Wc computed below with explicit pointers)
    grid_barrier();

    // ===== Phase 2: conv2, ic split 4-ways across adjacent lanes ===========
    {
        int h  = gtid & 3;           // ic quarter
        int p  = gtid >> 2;          // output index, < 16384
        int ox = p & 7;
        int oy = (p >> 3) & 7;
        int oc = (p >> 6) & 63;
        int b  = p >> 12;

        float sA = 0.f, sV = 0.f;
        int ic0 = h * 8;
        #pragma unroll 2
        for (int ic = ic0; ic < ic0 + 8; ic++) {
            const float2* avp = (const float2*)g_av + (b*C1 + ic) * 256;
            const float*  wp  = w2 + (oc*C1 + ic) * 16;
            #pragma unroll
            for (int ky = 0; ky < 4; ky++) {
                int iy = oy*2 - 1 + ky;
                if (iy < 0 || iy >= 16) continue;
                #pragma unroll
                for (int kx = 0; kx < 4; kx++) {
                    int ix = ox*2 - 1 + kx;
                    if (ix < 0 || ix >= 16) continue;
                    float wv = __ldg(&wp[ky*4 + kx]);
                    float2 av = __ldg(&avp[iy*16 + ix]);
                    sA += av.x * wv;
                    sV += av.y * wv;
                }
            }
        }
        sA += __shfl_xor_sync(0xFFFFFFFFu, sA, 1);
        sV += __shfl_xor_sync(0xFFFFFFFFu, sV, 1);
        sA += __shfl_xor_sync(0xFFFFFFFFu, sA, 2);
        sV += __shfl_xor_sync(0xFFFFFFFFu, sV, 2);
        if (h == 0) {
            float pre = sA + b2[oc];
            g_zq[(b*C2 + oc) * 64 + (oy*8 + ox)] = (pre > 0.f) ? sV : 0.f;
        }
    }
    grid_barrier();

    // ===== Phase 3: hopfield.  block -> (ng, b) ============================
    int n0 = (blockIdx.x & 31) * NTOK;
    int b  = blockIdx.x >> 5;

    // stage Wc (ready since barrier 1... it is written in phase 1 by wc
    // threads; see below) and tokens
    {
        const float4* W4 = (const float4*)g_Wc;
        ((float4*)WcS)[tid]       = __ldg(&W4[tid]);
        ((float4*)WcS)[tid + THR] = __ldg(&W4[tid + THR]);
    }
    if (tid < DD*NTOK) {
        int j = tid & 1, d = tid >> 1;
        tS[d*NTOK + j] = g_zq[(b*C2 + d)*64 + n0 + j];
    }
    __syncthreads();

    // --- scores: thread owns row m = tid, 2 tokens ---
    float a0 = 0.f, a1 = 0.f;
    {
        const float4* lrow = (const float4*)&Lsm[tid*LSTR];
        #pragma unroll
        for (int q = 0; q < 16; q++) {
            float4 l  = lrow[q];
            float4 t0 = *(const float4*)&tS[q*8];
            float4 t1 = *(const float4*)&tS[q*8 + 4];
            a0 += l.x*t0.x + l.y*t0.z + l.z*t1.x + l.w*t1.z;
            a1 += l.x*t0.y + l.y*t0.w + l.z*t1.y + l.w*t1.w;
        }
    }
    a0 *= 0.125f; a1 *= 0.125f;   // 1/sqrt(64)

    // --- block max ---
    {
        float mx0 = a0, mx1 = a1;
        #pragma unroll
        for (int o = 16; o > 0; o >>= 1) {
            mx0 = fmaxf(mx0, __shfl_xor_sync(0xFFFFFFFFu, mx0, o));
            mx1 = fmaxf(mx1, __shfl_xor_sync(0xFFFFFFFFu, mx1, o));
        }
        if (lane == 0) red2[wid] = make_float2(mx0, mx1);
    }
    __syncthreads();
    if (tid < 32) {
        float2 v = (lane < 16) ? red2[lane] : make_float2(-1e30f, -1e30f);
        #pragma unroll
        for (int o = 8; o > 0; o >>= 1) {
            v.x = fmaxf(v.x, __shfl_xor_sync(0xFFFFFFFFu, v.x, o));
            v.y = fmaxf(v.y, __shfl_xor_sync(0xFFFFFFFFu, v.y, o));
        }
        if (lane == 0) red2[16] = v;
    }
    __syncthreads();
    float2 MX = red2[16];

    // --- exp + block sum ---
    float e0 = __expf(a0 - MX.x);
    float e1 = __expf(a1 - MX.y);
    pS2[tid] = make_float2(e0, e1);
    {
        float s0 = e0, s1 = e1;
        #pragma unroll
        for (int o = 16; o > 0; o >>= 1) {
            s0 += __shfl_xor_sync(0xFFFFFFFFu, s0, o);
            s1 += __shfl_xor_sync(0xFFFFFFFFu, s1, o);
        }
        if (lane == 0) red2[wid] = make_float2(s0, s1);
    }
    __syncthreads();
    if (tid < 32) {
        float2 v = (lane < 16) ? red2[lane] : make_float2(0.f, 0.f);
        #pragma unroll
        for (int o = 8; o > 0; o >>= 1) {
            v.x += __shfl_xor_sync(0xFFFFFFFFu, v.x, o);
            v.y += __shfl_xor_sync(0xFFFFFFFFu, v.y, o);
        }
        if (lane == 0) red2[17] = v;
    }
    __syncthreads();
    float2 SUM = red2[17];

    // --- retrieval: part[c][d] = sum over 64 m of p[m]*L[m][d] ---
    {
        int d = tid & 63, c = tid >> 6;   // 8 chunks of 64 m
        float r0 = 0.f, r1 = 0.f;
        int m0 = c * 64;
        #pragma unroll 8
        for (int mm = 0; mm < 64; mm++) {
            float2 p = pS2[m0 + mm];              // broadcast
            float  l = Lsm[(m0 + mm)*LSTR + d];   // conflict-free
            r0 += p.x*l; r1 += p.y*l;
        }
        part2[c*64 + d] = make_float2(r0, r1);
    }
    __syncthreads();
    if (tid < NTOK*DD) {
        int j = tid >> 6, d = tid & 63;
        const float* pf = (const float*)part2;
        float s = 0.f;
        #pragma unroll
        for (int c = 0; c < 8; c++)
            s += pf[(c*64 + d)*2 + j];
        float inv = 1.f / (j ? SUM.y : SUM.x);
        tS[j*DD + d] = s * inv;                   // reuse tS as tmp[j][d]
    }
    __syncthreads();

    // --- projection: out[j][e] = sum_d tmp[j][d] * Wc[d][e] ---
    if (tid < NTOK*DD) {
        int j = tid >> 6, e = tid & 63;
        float o = 0.f;
        const float* tp = &tS[j*DD];
        #pragma unroll 16
        for (int d = 0; d < DD; d++)
            o += tp[d] * WcS[d*DD + e];           // bcast + conflict-free
        ((float*)&oS2[e])[j] = o;
    }
    __syncthreads();
    if (tid < DD) {
        float2 ov = oS2[tid];
        *(float2*)&out[(b*C2 + tid)*64 + n0] = ov;
    }
}

// ---------------------------------------------------------------------------
// Tiny helper kernel is NOT used; Wc must be computed inside fused_kernel.
// We fold it into phase 1 via extra pointers smuggled through __device__
// globals set by a 1-thread setup kernel? Not allowed (extra launch).
// Instead: Wc threads live in fused_kernel phase 1 using Wv/Wo passed as
// additional arguments below.
// ---------------------------------------------------------------------------
__global__ __launch_bounds__(THR, 1)
void fused_kernel_full(const float* __restrict__ x,
                       const float* __restrict__ w1,
                       const float* __restrict__ b1,
                       const float* __restrict__ w2,
                       const float* __restrict__ b2,
                       const float* __restrict__ lookup,
                       const float* __restrict__ Wv,
                       const float* __restrict__ Wo,
                       float* __restrict__ out);

extern "C" void kernel_launch(void* const* d_in, const int* in_sizes, int n_in,
                              void* d_out, int out_size) {
    const float* x       = (const float*)d_in[0];
    const float* conv1_w = (const float*)d_in[1];
    const float* conv1_b = (const float*)d_in[2];
    const float* conv2_w = (const float*)d_in[3];
    const float* conv2_b = (const float*)d_in[4];
    const float* lookup  = (const float*)d_in[5];
    const float* Wv      = (const float*)d_in[6];
    const float* Wo      = (const float*)d_in[7];
    float* out = (float*)d_out;

    const int smem_floats = MM*LSTR + DD*DD + MM*2 + MM*2
                          + DD*NTOK + DD*2 + 40;
    const size_t smem_bytes = smem_floats * sizeof(float);

    cudaFuncSetAttribute(fused_kernel_full,
                         cudaFuncAttributeMaxDynamicSharedMemorySize,
                         (int)smem_bytes);
    cudaFuncSetAttribute(fused_kernel_full,
                         cudaFuncAttributePreferredSharedMemoryCarveout, 100);

    fused_kernel_full<<<NBLK, THR, smem_bytes>>>(
        x, conv1_w, conv1_b, conv2_w, conv2_b, lookup, Wv, Wo, out);
}

// Full definition (phase 1 includes Wc computation with Wv/Wo).
__global__ __launch_bounds__(THR, 1)
void fused_kernel_full(const float* __restrict__ x,
                       const float* __restrict__ w1,
                       const float* __restrict__ b1,
                       const float* __restrict__ w2,
                       const float* __restrict__ b2,
                       const float* __restrict__ lookup,
                       const float* __restrict__ Wv,
                       const float* __restrict__ Wo,
                       float* __restrict__ out) {
    extern __shared__ float smem[];
    float*  Lsm   = smem;
    float*  WcS   = Lsm + MM*LSTR;
    float2* pS2   = (float2*)(WcS + DD*DD);
    float2* part2 = pS2 + MM;
    float*  tS    = (float*)(part2 + MM);
    float2* oS2   = (float2*)(tS + DD*NTOK);
    float2* red2  = oS2 + DD;

    int tid  = threadIdx.x;
    int lane = tid & 31;
    int wid  = tid >> 5;
    int gtid = blockIdx.x * THR + tid;

    // Phase 0: stage lookup
    {
        const float4* L4   = (const float4*)lookup;
        float4*       Lsm4 = (float4*)Lsm;
        #pragma unroll
        for (int batch = 0; batch < 2; batch++) {
            float4 v[8];
            #pragma unroll
            for (int u = 0; u < 8; u++)
                v[u] = __ldg(&L4[(batch*8 + u)*THR + tid]);
            #pragma unroll
            for (int u = 0; u < 8; u++) {
                int f = (batch*8 + u)*THR + tid;
                Lsm4[(f >> 4)*17 + (f & 15)] = v[u];
            }
        }
    }

    // Phase 1: conv1 + Wc
    if (gtid < BB*C1*16*16) {
        int idx = gtid;
        int ox = idx & 15;
        int oy = (idx >> 4) & 15;
        int oc = (idx >> 8) & 31;
        int b  = idx >> 13;
        float s = 0.f;
        #pragma unroll
        for (int ic = 0; ic < CIN; ic++) {
            const float* xp = x + (b*CIN + ic) * 1024;
            const float* wp = w1 + (oc*CIN + ic) * 16;
            #pragma unroll
            for (int ky = 0; ky < 4; ky++) {
                int iy = oy*2 - 1 + ky;
                if (iy < 0 || iy >= 32) continue;
                #pragma unroll
                for (int kx = 0; kx < 4; kx++) {
                    int ix = ox*2 - 1 + kx;
                    if (ix < 0 || ix >= 32) continue;
                    s += __ldg(&xp[iy*32 + ix]) * __ldg(&wp[ky*4 + kx]);
                }
            }
        }
        float pre = s + b1[oc];
        bool on = pre > 0.f;
        *(float2*)&g_av[2*idx] = make_float2(on ? pre : 0.f, on ? s : 0.f);
    } else if (gtid < BB*C1*16*16 + DD*DD) {
        int i = gtid - BB*C1*16*16;
        int d = i >> 6, e = i & 63;
        float s = 0.f;
        #pragma unroll 16
        for (int k = 0; k < DD; k++)
            s += __ldg(&Wv[d*DD + k]) * __ldg(&Wo[k*DD + e]);
        g_Wc[d*DD + e] = s;
    }
    grid_barrier();

    // Phase 2: conv2, ic split 4-ways
    {
        int h  = gtid & 3;
        int p  = gtid >> 2;
        int ox = p & 7;
        int oy = (p >> 3) & 7;
        int oc = (p >> 6) & 63;
        int b  = p >> 12;

        float sA = 0.f, sV = 0.f;
        int ic0 = h * 8;
        #pragma unroll 2
        for (int ic = ic0; ic < ic0 + 8; ic++) {
            const float2* avp = (const float2*)g_av + (b*C1 + ic) * 256;
            const float*  wp  = w2 + (oc*C1 + ic) * 16;
            #pragma unroll
            for (int ky = 0; ky < 4; ky++) {
                int iy = oy*2 - 1 + ky;
                if (iy < 0 || iy >= 16) continue;
                #pragma unroll
                for (int kx = 0; kx < 4; kx++) {
                    int ix = ox*2 - 1 + kx;
                    if (ix < 0 || ix >= 16) continue;
                    float wv = __ldg(&wp[ky*4 + kx]);
                    float2 av = __ldg(&avp[iy*16 + ix]);
                    sA += av.x * wv;
                    sV += av.y * wv;
                }
            }
        }
        sA += __shfl_xor_sync(0xFFFFFFFFu, sA, 1);
        sV += __shfl_xor_sync(0xFFFFFFFFu, sV, 1);
        sA += __shfl_xor_sync(0xFFFFFFFFu, sA, 2);
        sV += __shfl_xor_sync(0xFFFFFFFFu, sV, 2);
        if (h == 0) {
            float pre = sA + b2[oc];
            g_zq[(b*C2 + oc) * 64 + (oy*8 + ox)] = (pre > 0.f) ? sV : 0.f;
        }
    }
    grid_barrier();

    // Phase 3: hopfield
    int n0 = (blockIdx.x & 31) * NTOK;
    int b  = blockIdx.x >> 5;

    {
        const float4* W4 = (const float4*)g_Wc;
        ((float4*)WcS)[tid]       = __ldg(&W4[tid]);
        ((float4*)WcS)[tid + THR] = __ldg(&W4[tid + THR]);
    }
    if (tid < DD*NTOK) {
        int j = tid & 1, d = tid >> 1;
        tS[d*NTOK + j] = g_zq[(b*C2 + d)*64 + n0 + j];
    }
    __syncthreads();

    float a0 = 0.f, a1 = 0.f;
    {
        const float4* lrow = (const float4*)&Lsm[tid*LSTR];
        #pragma unroll
        for (int q = 0; q < 16; q++) {
            float4 l  = lrow[q];
            float4 t0 = *(const float4*)&tS[q*8];
            float4 t1 = *(const float4*)&tS[q*8 + 4];
            a0 += l.x*t0.x + l.y*t0.z + l.z*t1.x + l.w*t1.z;
            a1 += l.x*t0.y + l.y*t0.w + l.z*t1.y + l.w*t1.w;
        }
    }
    a0 *= 0.125f; a1 *= 0.125f;

    {
        float mx0 = a0, mx1 = a1;
        #pragma unroll
        for (int o = 16; o > 0; o >>= 1) {
            mx0 = fmaxf(mx0, __shfl_xor_sync(0xFFFFFFFFu, mx0, o));
            mx1 = fmaxf(mx1, __shfl_xor_sync(0xFFFFFFFFu, mx1, o));
        }
        if (lane == 0) red2[wid] = make_float2(mx0, mx1);
    }
    __syncthreads();
    if (tid < 32) {
        float2 v = (lane < 16) ? red2[lane] : make_float2(-1e30f, -1e30f);
        #pragma unroll
        for (int o = 8; o > 0; o >>= 1) {
            v.x = fmaxf(v.x, __shfl_xor_sync(0xFFFFFFFFu, v.x, o));
            v.y = fmaxf(v.y, __shfl_xor_sync(0xFFFFFFFFu, v.y, o));
        }
        if (lane == 0) red2[16] = v;
    }
    __syncthreads();
    float2 MX = red2[16];

    float e0 = __expf(a0 - MX.x);
    float e1 = __expf(a1 - MX.y);
    pS2[tid] = make_float2(e0, e1);
    {
        float s0 = e0, s1 = e1;
        #pragma unroll
        for (int o = 16; o > 0; o >>= 1) {
            s0 += __shfl_xor_sync(0xFFFFFFFFu, s0, o);
            s1 += __shfl_xor_sync(0xFFFFFFFFu, s1, o);
        }
        if (lane == 0) red2[wid] = make_float2(s0, s1);
    }
    __syncthreads();
    if (tid < 32) {
        float2 v = (lane < 16) ? red2[lane] : make_float2(0.f, 0.f);
        #pragma unroll
        for (int o = 8; o > 0; o >>= 1) {
            v.x += __shfl_xor_sync(0xFFFFFFFFu, v.x, o);
            v.y += __shfl_xor_sync(0xFFFFFFFFu, v.y, o);
        }
        if (lane == 0) red2[17] = v;
    }
    __syncthreads();
    float2 SUM = red2[17];

    {
        int d = tid & 63, c = tid >> 6;
        float r0 = 0.f, r1 = 0.f;
        int m0 = c * 64;
        #pragma unroll 8
        for (int mm = 0; mm < 64; mm++) {
            float2 p = pS2[m0 + mm];
            float  l = Lsm[(m0 + mm)*LSTR + d];
            r0 += p.x*l; r1 += p.y*l;
        }
        part2[c*64 + d] = make_float2(r0, r1);
    }
    __syncthreads();
    if (tid < NTOK*DD) {
        int j = tid >> 6, d = tid & 63;
        const float* pf = (const float*)part2;
        float s = 0.f;
        #pragma unroll
        for (int c = 0; c < 8; c++)
            s += pf[(c*64 + d)*2 + j];
        float inv = 1.f / (j ? SUM.y : SUM.x);
        tS[j*DD + d] = s * inv;
    }
    __syncthreads();

    if (tid < NTOK*DD) {
        int j = tid >> 6, e = tid & 63;
        float o = 0.f;
        const float* tp = &tS[j*DD];
        #pragma unroll 16
        for (int d = 0; d < DD; d++)
            o += tp[d] * WcS[d*DD + e];
        ((float*)&oS2[e])[j] = o;
    }
    __syncthreads();
    if (tid < DD) {
        float2 ov = oS2[tid];
        *(float2*)&out[(b*C2 + tid)*64 + n0] = ov;
    }
}